// round 5
// baseline (speedup 1.0000x reference)
#include <cuda_runtime.h>
#include <cstdint>

#define NN 20000
#define EE 320000
#define HH 280
#define GG 64
#define NFF 5
#define EFF 4
#define LL 3
#define ZZ 64
#define K_MSG 564   // 2H + EF
#define K_UPD 560   // 2H

// ---------------- scratch (static device globals; no runtime alloc) ----------------
__device__ float g_h[NN * HH];        // node features
__device__ float g_Y[EE * HH];        // edge hidden / message (in-place GEMM2)
__device__ float g_agg[NN * HH];      // aggregated messages
__device__ float g_U[NN * HH];        // update hidden (in-place GEMM2)
__device__ float g_stats[2 * HH];     // column sum / sumsq
__device__ float g_scale[HH];         // bn scale  (g * rstd)
__device__ float g_shift[HH];         // bn shift  (be - mean*scale)
__device__ float g_pool[GG * HH];
__device__ float g_cnt[GG];

// ---------------- f32x2 helpers (Blackwell packed fp32) ----------------
__device__ __forceinline__ uint64_t f32x2_fma(uint64_t a, uint64_t b, uint64_t c) {
    uint64_t d;
    asm("fma.rn.f32x2 %0, %1, %2, %3;" : "=l"(d) : "l"(a), "l"(b), "l"(c));
    return d;
}
__device__ __forceinline__ uint64_t f32_rep2(float x) {
    uint64_t d;
    asm("mov.b64 %0, {%1, %1};" : "=l"(d) : "f"(x));
    return d;
}

// ---------------- generic zero ----------------
__global__ void zero_kernel(float* __restrict__ p, int n) {
    int i = blockIdx.x * 256 + threadIdx.x;
    if (i < n) p[i] = 0.f;
}

// ---------------- input layer: h = x @ Wi + bi ----------------
__global__ void input_layer(const float* __restrict__ x, const float* __restrict__ Wi,
                            const float* __restrict__ bi, float* __restrict__ h) {
    int idx = blockIdx.x * 256 + threadIdx.x;
    if (idx >= NN * HH) return;
    int n = idx / HH;
    int c = idx - n * HH;
    float s = bi[c];
#pragma unroll
    for (int f = 0; f < NFF; f++) s = fmaf(x[n * NFF + f], Wi[f * HH + c], s);
    h[idx] = s;
}

// ---------------- GEMM over concatenated gathered inputs ----------------
// C[M, 280] = cat(A0[idx0], A1[idx1], A2?) @ W[K,280] + bias
// BM=128, BN=280 (full), BK=8, 320 threads, thread tile 4 rows x 28 cols (14 f32x2 pairs)
__global__ __launch_bounds__(320, 1)
void gemm_cat(const float* __restrict__ A0, const int* __restrict__ idx0,
              const float* __restrict__ A1, const int* __restrict__ idx1,
              const float* __restrict__ A2,
              const float* __restrict__ W, const float* __restrict__ bias,
              float* __restrict__ C, int M, int K) {
    __shared__ __align__(16) float sA[8 * 128];
    __shared__ __align__(16) float sW[8 * HH];
    __shared__ int sI0[128];
    __shared__ int sI1[128];

    const int tid = threadIdx.x;
    const int row0 = blockIdx.x * 128;
    if (tid < 128) {
        int e = row0 + tid;
        if (e >= M) e = M - 1;
        sI0[tid] = idx0 ? idx0[e] : e;
        sI1[tid] = idx1 ? idx1[e] : e;
    }
    const int rg = tid / 10;        // 0..31
    const int cg = tid - rg * 10;   // 0..9
    const int colbase = cg * 28;

    uint64_t acc[56];
#pragma unroll
    for (int j = 0; j < 14; j++) {
        uint64_t b2 = *reinterpret_cast<const uint64_t*>(bias + colbase + 2 * j);
#pragma unroll
        for (int i = 0; i < 4; i++) acc[i * 14 + j] = b2;
    }

    const int nCh = (K + 7) >> 3;
    for (int ch = 0; ch < nCh; ++ch) {
        const int kbase = ch * 8;
        __syncthreads();
        // ---- A tile (gathered), transposed into sA[k][row]
        if (tid < 256) {
            const int r = tid >> 1;
            const int kk = (tid & 1) * 4;
            float4 v;
            if (kbase < HH) {
                const float* p = A0 + (long)sI0[r] * HH + kbase + kk;
                v = *reinterpret_cast<const float4*>(p);
            } else if (kbase < 2 * HH) {
                const float* p = A1 + (long)sI1[r] * HH + (kbase - HH) + kk;
                v = *reinterpret_cast<const float4*>(p);
            } else {
                if (kk == 0) {
                    int e = row0 + r;
                    v = *reinterpret_cast<const float4*>(A2 + (long)e * EFF);
                } else {
                    v = make_float4(0.f, 0.f, 0.f, 0.f);
                }
            }
            sA[(kk + 0) * 128 + r] = v.x;
            sA[(kk + 1) * 128 + r] = v.y;
            sA[(kk + 2) * 128 + r] = v.z;
            sA[(kk + 3) * 128 + r] = v.w;
        }
        // ---- W tile: rows kbase..kbase+7 (contiguous 2240 floats)
        {
            const float* wsrc = W + (long)kbase * HH;
            const int valid = (K - kbase >= 8) ? 8 * HH : (K - kbase) * HH;
#pragma unroll
            for (int i = 0; i < 7; i++) {
                int id = tid + i * 320;
                sW[id] = (id < valid) ? wsrc[id] : 0.f;
            }
        }
        __syncthreads();
#pragma unroll
        for (int k = 0; k < 8; k++) {
            float4 a = *reinterpret_cast<const float4*>(sA + k * 128 + rg * 4);
            uint64_t a2[4];
            a2[0] = f32_rep2(a.x); a2[1] = f32_rep2(a.y);
            a2[2] = f32_rep2(a.z); a2[3] = f32_rep2(a.w);
            const ulonglong2* wp = reinterpret_cast<const ulonglong2*>(sW + k * HH + colbase);
            uint64_t w[14];
#pragma unroll
            for (int j = 0; j < 7; j++) { ulonglong2 u = wp[j]; w[2 * j] = u.x; w[2 * j + 1] = u.y; }
#pragma unroll
            for (int i = 0; i < 4; i++)
#pragma unroll
                for (int j = 0; j < 14; j++)
                    acc[i * 14 + j] = f32x2_fma(a2[i], w[j], acc[i * 14 + j]);
        }
    }
#pragma unroll
    for (int i = 0; i < 4; i++) {
        int row = row0 + rg * 4 + i;
        if (row < M) {
            uint64_t* out = reinterpret_cast<uint64_t*>(C + (long)row * HH + colbase);
#pragma unroll
            for (int j = 0; j < 14; j++) out[j] = acc[i * 14 + j];
        }
    }
}

// ---------------- in-place GEMM with fused BN+ReLU on the input read ----------------
// C[M,280] = relu(bn(C)) @ W[280,280] + bias   (bn params in g_scale/g_shift)
__global__ __launch_bounds__(320, 1)
void gemm_inplace(float* __restrict__ C, const float* __restrict__ W,
                  const float* __restrict__ bias, int M) {
    __shared__ __align__(16) float sA[8 * 128];
    __shared__ __align__(16) float sW[8 * HH];
    __shared__ __align__(16) float sScale[HH];
    __shared__ __align__(16) float sShift[HH];

    const int tid = threadIdx.x;
    const int row0 = blockIdx.x * 128;
    if (tid < HH) {
        sScale[tid] = g_scale[tid];
        sShift[tid] = g_shift[tid];
    }
    const int rg = tid / 10;
    const int cg = tid - rg * 10;
    const int colbase = cg * 28;

    uint64_t acc[56];
#pragma unroll
    for (int j = 0; j < 14; j++) {
        uint64_t b2 = *reinterpret_cast<const uint64_t*>(bias + colbase + 2 * j);
#pragma unroll
        for (int i = 0; i < 4; i++) acc[i * 14 + j] = b2;
    }

    const int nCh = HH / 8;  // 35
    for (int ch = 0; ch < nCh; ++ch) {
        const int kbase = ch * 8;
        __syncthreads();
        if (tid < 256) {
            const int r = tid >> 1;
            const int kk = (tid & 1) * 4;
            int row = row0 + r;
            if (row >= M) row = M - 1;
            float4 v = *reinterpret_cast<const float4*>(C + (long)row * HH + kbase + kk);
            float4 s = *reinterpret_cast<const float4*>(sScale + kbase + kk);
            float4 t = *reinterpret_cast<const float4*>(sShift + kbase + kk);
            v.x = fmaxf(fmaf(v.x, s.x, t.x), 0.f);
            v.y = fmaxf(fmaf(v.y, s.y, t.y), 0.f);
            v.z = fmaxf(fmaf(v.z, s.z, t.z), 0.f);
            v.w = fmaxf(fmaf(v.w, s.w, t.w), 0.f);
            sA[(kk + 0) * 128 + r] = v.x;
            sA[(kk + 1) * 128 + r] = v.y;
            sA[(kk + 2) * 128 + r] = v.z;
            sA[(kk + 3) * 128 + r] = v.w;
        }
        {
            const float* wsrc = W + (long)kbase * HH;
#pragma unroll
            for (int i = 0; i < 7; i++) {
                int id = tid + i * 320;
                sW[id] = wsrc[id];
            }
        }
        __syncthreads();
#pragma unroll
        for (int k = 0; k < 8; k++) {
            float4 a = *reinterpret_cast<const float4*>(sA + k * 128 + rg * 4);
            uint64_t a2[4];
            a2[0] = f32_rep2(a.x); a2[1] = f32_rep2(a.y);
            a2[2] = f32_rep2(a.z); a2[3] = f32_rep2(a.w);
            const ulonglong2* wp = reinterpret_cast<const ulonglong2*>(sW + k * HH + colbase);
            uint64_t w[14];
#pragma unroll
            for (int j = 0; j < 7; j++) { ulonglong2 u = wp[j]; w[2 * j] = u.x; w[2 * j + 1] = u.y; }
#pragma unroll
            for (int i = 0; i < 4; i++)
#pragma unroll
                for (int j = 0; j < 14; j++)
                    acc[i * 14 + j] = f32x2_fma(a2[i], w[j], acc[i * 14 + j]);
        }
    }
#pragma unroll
    for (int i = 0; i < 4; i++) {
        int row = row0 + rg * 4 + i;
        if (row < M) {
            uint64_t* out = reinterpret_cast<uint64_t*>(C + (long)row * HH + colbase);
#pragma unroll
            for (int j = 0; j < 14; j++) out[j] = acc[i * 14 + j];
        }
    }
}

// ---------------- column stats (sum, sumsq) ----------------
__global__ void col_stats(const float* __restrict__ Y, int M) {
    int c = threadIdx.x;
    if (c >= HH) return;
    int rp = (M + gridDim.x - 1) / gridDim.x;
    int r0 = blockIdx.x * rp;
    int r1 = min(M, r0 + rp);
    float s = 0.f, s2 = 0.f;
    for (int r = r0; r < r1; ++r) {
        float v = Y[(long)r * HH + c];
        s += v;
        s2 = fmaf(v, v, s2);
    }
    atomicAdd(&g_stats[c], s);
    atomicAdd(&g_stats[HH + c], s2);
}

__global__ void finalize_stats(const float* __restrict__ g, const float* __restrict__ be,
                               float invM) {
    int c = threadIdx.x;
    if (c >= HH) return;
    float mean = g_stats[c] * invM;
    float var = g_stats[HH + c] * invM - mean * mean;
    float rstd = rsqrtf(var + 1e-5f);
    float sc = g[c] * rstd;
    g_scale[c] = sc;
    g_shift[c] = fmaf(-mean, sc, be[c]);
}

// ---------------- scatter: agg[dst[e]] += relu(bn(Y[e])) ----------------
__global__ void scatter_bn_relu(const float* __restrict__ Y, const int* __restrict__ dst,
                                float* __restrict__ agg) {
    long idx = (long)blockIdx.x * 256 + threadIdx.x;
    if (idx >= (long)EE * HH) return;
    int e = (int)(idx / HH);
    int c = (int)(idx - (long)e * HH);
    float v = fmaf(Y[idx], g_scale[c], g_shift[c]);
    if (v > 0.f) atomicAdd(&agg[dst[e] * HH + c], v);
}

// ---------------- residual: h += relu(bn(U)) ----------------
__global__ void residual_bn_relu(const float* __restrict__ U, float* __restrict__ h) {
    int idx = blockIdx.x * 256 + threadIdx.x;
    if (idx >= NN * HH) return;
    int c = idx % HH;
    float v = fmaf(U[idx], g_scale[c], g_shift[c]);
    h[idx] += fmaxf(v, 0.f);
}

// ---------------- pooling ----------------
__global__ void pool_accum(const float* __restrict__ h, const int* __restrict__ batch,
                           float* __restrict__ pool) {
    int idx = blockIdx.x * 256 + threadIdx.x;
    if (idx >= NN * HH) return;
    int n = idx / HH;
    int c = idx - n * HH;
    atomicAdd(&pool[batch[n] * HH + c], h[idx]);
}

__global__ void pool_count(const int* __restrict__ batch, float* __restrict__ cnt) {
    int n = blockIdx.x * 256 + threadIdx.x;
    if (n < NN) atomicAdd(&cnt[batch[n]], 1.0f);
}

// ---------------- head: out[g,z] = (pool[g]/cnt[g]) @ Wmu + bmu ----------------
__global__ void head_kernel(const float* __restrict__ pool, const float* __restrict__ cnt,
                            const float* __restrict__ Wmu, const float* __restrict__ bmu,
                            float* __restrict__ out) {
    int gph = blockIdx.x;
    int z = threadIdx.x;
    float inv = 1.0f / fmaxf(cnt[gph], 1.0f);
    float s = bmu[z];
    for (int k = 0; k < HH; k++) s = fmaf(pool[gph * HH + k] * inv, Wmu[k * ZZ + z], s);
    out[gph * ZZ + z] = s;
}

// ---------------- host orchestration ----------------
extern "C" void kernel_launch(void* const* d_in, const int* in_sizes, int n_in,
                              void* d_out, int out_size) {
    const float *x, *edge_attr, *Wi, *bi, *Wm1, *bm1, *g1, *be1, *Wm2, *bm2, *g2, *be2;
    const float *Wu1, *bu1, *g3, *be3, *Wu2, *bu2, *g4, *be4, *Wmu, *bmu;
    const int *edge_index, *batch;

    if (in_sizes[2] == 2 * EE) {
        // setup_inputs() dict order
        x = (const float*)d_in[0];   edge_attr = (const float*)d_in[1];
        edge_index = (const int*)d_in[2]; batch = (const int*)d_in[3];
        Wi = (const float*)d_in[4];  bi = (const float*)d_in[5];
        Wm1 = (const float*)d_in[6]; bm1 = (const float*)d_in[7];
        g1 = (const float*)d_in[8];  be1 = (const float*)d_in[9];
        Wm2 = (const float*)d_in[10]; bm2 = (const float*)d_in[11];
        g2 = (const float*)d_in[12]; be2 = (const float*)d_in[13];
        Wu1 = (const float*)d_in[14]; bu1 = (const float*)d_in[15];
        g3 = (const float*)d_in[16]; be3 = (const float*)d_in[17];
        Wu2 = (const float*)d_in[18]; bu2 = (const float*)d_in[19];
        g4 = (const float*)d_in[20]; be4 = (const float*)d_in[21];
        Wmu = (const float*)d_in[22]; bmu = (const float*)d_in[23];
    } else {
        // reference() signature order
        x = (const float*)d_in[0];   edge_attr = (const float*)d_in[1];
        Wi = (const float*)d_in[2];  bi = (const float*)d_in[3];
        Wm1 = (const float*)d_in[4]; bm1 = (const float*)d_in[5];
        g1 = (const float*)d_in[6];  be1 = (const float*)d_in[7];
        Wm2 = (const float*)d_in[8]; bm2 = (const float*)d_in[9];
        g2 = (const float*)d_in[10]; be2 = (const float*)d_in[11];
        Wu1 = (const float*)d_in[12]; bu1 = (const float*)d_in[13];
        g3 = (const float*)d_in[14]; be3 = (const float*)d_in[15];
        Wu2 = (const float*)d_in[16]; bu2 = (const float*)d_in[17];
        g4 = (const float*)d_in[18]; be4 = (const float*)d_in[19];
        Wmu = (const float*)d_in[20]; bmu = (const float*)d_in[21];
        edge_index = (const int*)d_in[22]; batch = (const int*)d_in[23];
    }
    const int* src = edge_index;
    const int* dst = edge_index + EE;

    float *hbuf, *Ybuf, *aggbuf, *Ubuf, *poolbuf, *cntbuf, *statsbuf;
    cudaGetSymbolAddress((void**)&hbuf, g_h);
    cudaGetSymbolAddress((void**)&Ybuf, g_Y);
    cudaGetSymbolAddress((void**)&aggbuf, g_agg);
    cudaGetSymbolAddress((void**)&Ubuf, g_U);
    cudaGetSymbolAddress((void**)&poolbuf, g_pool);
    cudaGetSymbolAddress((void**)&cntbuf, g_cnt);
    cudaGetSymbolAddress((void**)&statsbuf, g_stats);

    const int NH_BLKS = (NN * HH + 255) / 256;        // 21875
    const int MSG_BLKS = EE / 128;                    // 2500
    const int UPD_BLKS = (NN + 127) / 128;            // 157
    const long EH = (long)EE * HH;
    const int SC_BLKS = (int)((EH + 255) / 256);      // 350000

    input_layer<<<NH_BLKS, 256>>>(x, Wi, bi, hbuf);

    for (int l = 0; l < LL; l++) {
        const float* wm1 = Wm1 + (long)l * K_MSG * HH;
        const float* wm2 = Wm2 + (long)l * HH * HH;
        const float* wu1 = Wu1 + (long)l * K_UPD * HH;
        const float* wu2 = Wu2 + (long)l * HH * HH;

        // ---- message MLP on edges ----
        gemm_cat<<<MSG_BLKS, 320>>>(hbuf, dst, hbuf, src, edge_attr,
                                    wm1, bm1 + l * HH, Ybuf, EE, K_MSG);
        zero_kernel<<<3, 256>>>(statsbuf, 2 * HH);
        col_stats<<<1024, 288>>>(Ybuf, EE);
        finalize_stats<<<1, 288>>>(g1 + l * HH, be1 + l * HH, 1.0f / EE);
        gemm_inplace<<<MSG_BLKS, 320>>>(Ybuf, wm2, bm2 + l * HH, EE);
        zero_kernel<<<3, 256>>>(statsbuf, 2 * HH);
        col_stats<<<1024, 288>>>(Ybuf, EE);
        finalize_stats<<<1, 288>>>(g2 + l * HH, be2 + l * HH, 1.0f / EE);

        // ---- aggregate ----
        zero_kernel<<<NH_BLKS, 256>>>(aggbuf, NN * HH);
        scatter_bn_relu<<<SC_BLKS, 256>>>(Ybuf, dst, aggbuf);

        // ---- update MLP on nodes ----
        gemm_cat<<<UPD_BLKS, 320>>>(hbuf, nullptr, aggbuf, nullptr, nullptr,
                                    wu1, bu1 + l * HH, Ubuf, NN, K_UPD);
        zero_kernel<<<3, 256>>>(statsbuf, 2 * HH);
        col_stats<<<160, 288>>>(Ubuf, NN);
        finalize_stats<<<1, 288>>>(g3 + l * HH, be3 + l * HH, 1.0f / NN);
        gemm_inplace<<<UPD_BLKS, 320>>>(Ubuf, wu2, bu2 + l * HH, NN);
        zero_kernel<<<3, 256>>>(statsbuf, 2 * HH);
        col_stats<<<160, 288>>>(Ubuf, NN);
        finalize_stats<<<1, 288>>>(g4 + l * HH, be4 + l * HH, 1.0f / NN);
        residual_bn_relu<<<NH_BLKS, 256>>>(Ubuf, hbuf);
    }

    // ---- global mean pool + mu head ----
    zero_kernel<<<(GG * HH + 255) / 256, 256>>>(poolbuf, GG * HH);
    zero_kernel<<<1, 256>>>(cntbuf, GG);
    pool_accum<<<NH_BLKS, 256>>>(hbuf, batch, poolbuf);
    pool_count<<<(NN + 255) / 256, 256>>>(batch, cntbuf);
    head_kernel<<<GG, ZZ>>>(poolbuf, cntbuf, Wmu, bmu, (float*)d_out);
}